// round 3
// baseline (speedup 1.0000x reference)
#include <cuda_runtime.h>
#include <cuda_fp16.h>
#include <stdint.h>

#define BB   256
#define LL   336
#define NIN  8
#define HH   512
#define G4   2048
#define PL   96
#define NBLK 256
#define NTHR 256

__device__ float  g_h0[2][BB*HH];
__device__ float  g_c0[BB*HH];
__device__ float  g_h1[2][BB*HH];
__device__ float  g_c1[BB*HH];
__device__ float  g_gb0[BB*G4];
__device__ float  g_gb1[BB*G4];
__device__ float  g_ctx[BB*HH];
__device__ float  g_yprev[BB];
__device__ __half g_enc[(size_t)LL*BB*HH];
__device__ float  g_Whh0r[G4*HH];
__device__ float  g_Wih1r[G4*HH];
__device__ float  g_Whh1r[G4*HH];
__device__ float  g_Wdir [G4*HH];
__device__ float  g_Wdhr [G4*HH];
__device__ float  g_bc0[G4], g_bc1[G4], g_bcd[G4], g_Wdi0[G4];
__device__ unsigned g_bar_enc, g_bar_dec;

__device__ __forceinline__ float rna_tf32(float x) {
    uint32_t r; asm("cvt.rna.tf32.f32 %0, %1;" : "=r"(r) : "f"(x));
    return __uint_as_float(r);
}
__device__ __forceinline__ float sigf(float x) { return 1.f / (1.f + __expf(-x)); }

__device__ __forceinline__ void gridbar(unsigned* bar, unsigned& round) {
    round++;
    __syncthreads();
    __threadfence();
    if (threadIdx.x == 0) {
        unsigned target = round * NBLK;
        atomicAdd(bar, 1u);
        while (*(volatile unsigned*)bar < target) { }
        __threadfence();
    }
    __syncthreads();
}

__device__ __forceinline__ void mma_tf32(float c[4], const uint32_t a[4],
                                         uint32_t b0, uint32_t b1) {
    asm volatile(
        "mma.sync.aligned.m16n8k8.row.col.f32.tf32.tf32.f32 "
        "{%0,%1,%2,%3},{%4,%5,%6,%7},{%8,%9},{%0,%1,%2,%3};"
        : "+f"(c[0]), "+f"(c[1]), "+f"(c[2]), "+f"(c[3])
        : "r"(a[0]), "r"(a[1]), "r"(a[2]), "r"(a[3]), "r"(b0), "r"(b1));
}

__global__ void prep_kernel(const float* __restrict__ Whh0, const float* __restrict__ Wih1,
                            const float* __restrict__ Whh1, const float* __restrict__ Wdi,
                            const float* __restrict__ Wdh,
                            const float* bi0, const float* bh0,
                            const float* bi1, const float* bh1,
                            const float* bdi, const float* bdh) {
    int i = blockIdx.x * blockDim.x + threadIdx.x;
    if (i < G4 * HH) {
        int j = i / HH, k = i - j * HH;
        g_Whh0r[i] = rna_tf32(Whh0[i]);
        g_Wih1r[i] = rna_tf32(Wih1[i]);
        g_Whh1r[i] = rna_tf32(Whh1[i]);
        g_Wdir[i]  = rna_tf32(Wdi[(size_t)j * (HH + 1) + 1 + k]);
        g_Wdhr[i]  = rna_tf32(Wdh[i]);
    }
    if (i < G4) {
        g_bc0[i] = bi0[i] + bh0[i];
        g_bc1[i] = bi1[i] + bh1[i];
        g_bcd[i] = bdi[i] + bdh[i];
        g_Wdi0[i] = Wdi[(size_t)i * (HH + 1)];
    }
    if (i < BB * HH) {
        g_h0[0][i] = 0.f; g_h0[1][i] = 0.f;
        g_h1[0][i] = 0.f; g_h1[1][i] = 0.f;
        g_c0[i] = 0.f;    g_c1[i] = 0.f;
    }
    if (i < BB) g_yprev[i] = 0.f;
    if (i == 0) { g_bar_enc = 0u; g_bar_dec = 0u; }
}

// one 64x64 tile of C[256,2048] = A[256,K] * W^T ; W row-major [2048,K]
__device__ void gemm_tile(const float* __restrict__ Alo, const float* __restrict__ Ahi,
                          const float* __restrict__ Wlo, const float* __restrict__ Whi,
                          float* __restrict__ C, int K, int mb, int nb, float* sm) {
    float* As = sm;            // [64][36]
    float* Bs = sm + 64 * 36;  // [64][36]
    int tid = threadIdx.x, lane = tid & 31, wid = tid >> 5;
    int wm = wid >> 2, wn = wid & 3;
    int lr = lane >> 2, lc = lane & 3;

    float acc[2][2][4];
#pragma unroll
    for (int a = 0; a < 2; a++)
#pragma unroll
        for (int b = 0; b < 2; b++)
#pragma unroll
            for (int q = 0; q < 4; q++) acc[a][b][q] = 0.f;

    int r = tid >> 3, k4 = (tid & 7) * 4;

    for (int kc = 0; kc < K; kc += 32) {
        const float* Ab = (kc < HH) ? Alo : Ahi;
        const float* Wb = (kc < HH) ? Wlo : Whi;
        int kl = kc & (HH - 1);
#pragma unroll
        for (int rr = 0; rr < 2; rr++) {
            int row = r + rr * 32;
            *(float4*)(&As[row * 36 + k4]) = *(const float4*)(Ab + (size_t)(mb + row) * HH + kl + k4);
            *(float4*)(&Bs[row * 36 + k4]) = *(const float4*)(Wb + (size_t)(nb + row) * HH + kl + k4);
        }
        __syncthreads();
#pragma unroll
        for (int k8 = 0; k8 < 4; k8++) {
            uint32_t af[2][4], bf[2][2];
#pragma unroll
            for (int mi = 0; mi < 2; mi++) {
                int mr = wm * 32 + mi * 16;
                af[mi][0] = __float_as_uint(As[(mr + lr    ) * 36 + k8 * 8 + lc    ]);
                af[mi][1] = __float_as_uint(As[(mr + 8 + lr) * 36 + k8 * 8 + lc    ]);
                af[mi][2] = __float_as_uint(As[(mr + lr    ) * 36 + k8 * 8 + lc + 4]);
                af[mi][3] = __float_as_uint(As[(mr + 8 + lr) * 36 + k8 * 8 + lc + 4]);
            }
#pragma unroll
            for (int ni = 0; ni < 2; ni++) {
                int nc = wn * 16 + ni * 8 + lr;
                bf[ni][0] = __float_as_uint(Bs[nc * 36 + k8 * 8 + lc    ]);
                bf[ni][1] = __float_as_uint(Bs[nc * 36 + k8 * 8 + lc + 4]);
            }
#pragma unroll
            for (int mi = 0; mi < 2; mi++)
#pragma unroll
                for (int ni = 0; ni < 2; ni++)
                    mma_tf32(acc[mi][ni], af[mi], bf[ni][0], bf[ni][1]);
        }
        __syncthreads();
    }

#pragma unroll
    for (int mi = 0; mi < 2; mi++)
#pragma unroll
        for (int ni = 0; ni < 2; ni++) {
            int row = mb + wm * 32 + mi * 16 + lr;
            int col = nb + wn * 16 + ni * 8 + 2 * lc;
            float* Cp = C + (size_t)row * G4 + col;
            Cp[0] = acc[mi][ni][0];
            Cp[1] = acc[mi][ni][1];
            Cp += (size_t)8 * G4;
            Cp[0] = acc[mi][ni][2];
            Cp[1] = acc[mi][ni][3];
        }
}

__global__ void __launch_bounds__(NTHR, 2) enc_persistent(const float* __restrict__ x,
                                                          const float* __restrict__ Wih0) {
    __shared__ float sm[64 * 36 * 2];
    unsigned round = 0;
    int bx = blockIdx.x;
    int t = bx * NTHR + threadIdx.x;

    for (int s = 0; s <= LL; s++) {
        // ---- GEMM phase ----
        if (bx < 128) {
            if (s < LL) {
                int mt = bx >> 5, nt = bx & 31;
                gemm_tile(g_h0[s & 1], nullptr, g_Whh0r, nullptr, g_gb0, HH,
                          mt * 64, nt * 64, sm);
            }
        } else {
            if (s >= 1) {
                int j = bx - 128;
                int mt = j >> 5, nt = j & 31;
                gemm_tile(g_h0[s & 1], g_h1[(s + 1) & 1], g_Wih1r, g_Whh1r, g_gb1, 2 * HH,
                          mt * 64, nt * 64, sm);
            }
        }
        gridbar(&g_bar_enc, round);

        // ---- cell phase ----
        if (s < LL) {
            float* h0w = g_h0[(s + 1) & 1];
#pragma unroll
            for (int it = 0; it < 2; it++) {
                int e = t + it * (NBLK * NTHR);
                int b = e >> 9, n = e & (HH - 1);
                const float* xp = x + ((size_t)b * LL + s) * NIN;
                float xv[8];
#pragma unroll
                for (int k = 0; k < 8; k++) xv[k] = xp[k];
                float gv[4];
#pragma unroll
                for (int gi = 0; gi < 4; gi++) {
                    int j = gi * HH + n;
                    float a = g_gb0[(size_t)b * G4 + j] + g_bc0[j];
                    const float* wr = Wih0 + j * 8;
#pragma unroll
                    for (int k = 0; k < 8; k++) a += wr[k] * xv[k];
                    gv[gi] = a;
                }
                float ig = sigf(gv[0]), fg = sigf(gv[1]);
                float gg = tanhf(gv[2]), og = sigf(gv[3]);
                float c = fg * g_c0[e] + ig * gg;
                g_c0[e] = c;
                h0w[e] = rna_tf32(og * tanhf(c));
            }
        }
        if (s >= 1) {
            float* h1w = g_h1[s & 1];
#pragma unroll
            for (int it = 0; it < 2; it++) {
                int e = t + it * (NBLK * NTHR);
                int b = e >> 9, n = e & (HH - 1);
                float gv[4];
#pragma unroll
                for (int gi = 0; gi < 4; gi++) {
                    int j = gi * HH + n;
                    gv[gi] = g_gb1[(size_t)b * G4 + j] + g_bc1[j];
                }
                float ig = sigf(gv[0]), fg = sigf(gv[1]);
                float gg = tanhf(gv[2]), og = sigf(gv[3]);
                float c = fg * g_c1[e] + ig * gg;
                g_c1[e] = c;
                float h = og * tanhf(c);
                g_enc[((size_t)(s - 1) * BB + b) * HH + n] = __float2half(h);
                h1w[e] = rna_tf32(h);
            }
        }
        gridbar(&g_bar_enc, round);
    }
}

__device__ __forceinline__ float dot8r(uint4 v, const float* s) {
    const __half2* h2 = (const __half2*)&v;
    float r = 0.f;
#pragma unroll
    for (int i = 0; i < 4; i++) {
        float2 f = __half22float2(h2[i]);
        r += f.x * s[2 * i] + f.y * s[2 * i + 1];
    }
    return r;
}

__device__ void attn_phase(int ds, int b, const float* __restrict__ Wfc,
                           const float* __restrict__ bfc, float* __restrict__ out, float* sm) {
    float* sh   = sm;          // 512
    float* sc   = sm + 512;    // 336
    float* red  = sm + 848;    // 256
    float* part = sm + 1104;   // 4*512
    int tid = threadIdx.x;
    const float* hd = g_h1[ds & 1] + (size_t)b * HH;

    red[tid] = hd[tid] * Wfc[tid] + hd[tid + 256] * Wfc[tid + 256];
    sh[tid] = hd[tid];
    sh[tid + 256] = hd[tid + 256];
    __syncthreads();
    for (int off = 128; off; off >>= 1) {
        if (tid < off) red[tid] += red[tid + off];
        __syncthreads();
    }
    if (tid == 0) {
        float y = red[0] + bfc[0];
        g_yprev[b] = (ds == 0) ? 0.f : y;
        if (ds > 0) out[b * PL + (ds - 1)] = y;
    }
    __syncthreads();

    int lane = tid & 31, w = tid >> 5;
    float hreg[16];
#pragma unroll
    for (int i = 0; i < 8; i++) {
        hreg[i]     = sh[lane * 8 + i];
        hreg[8 + i] = sh[256 + lane * 8 + i];
    }
    for (int l = w; l < LL; l += 8) {
        const uint4* e4 = (const uint4*)(g_enc + ((size_t)l * BB + b) * HH);
        uint4 v0 = e4[lane];
        uint4 v1 = e4[lane + 32];
        float s1 = dot8r(v0, hreg) + dot8r(v1, hreg + 8);
#pragma unroll
        for (int off = 16; off; off >>= 1) s1 += __shfl_xor_sync(0xffffffffu, s1, off);
        if (lane == 0) sc[l] = s1;
    }
    __syncthreads();

    float m = -1e30f;
    for (int l = tid; l < LL; l += 256) m = fmaxf(m, sc[l]);
    red[tid] = m;
    __syncthreads();
    for (int off = 128; off; off >>= 1) {
        if (tid < off) red[tid] = fmaxf(red[tid], red[tid + off]);
        __syncthreads();
    }
    float mx = red[0];
    __syncthreads();
    float lsum = 0.f;
    for (int l = tid; l < LL; l += 256) {
        float e = __expf(sc[l] - mx);
        sc[l] = e;
        lsum += e;
    }
    red[tid] = lsum;
    __syncthreads();
    for (int off = 128; off; off >>= 1) {
        if (tid < off) red[tid] += red[tid + off];
        __syncthreads();
    }

    int hg = tid & 63, lp = tid >> 6;
    float acc[8];
#pragma unroll
    for (int i = 0; i < 8; i++) acc[i] = 0.f;
    for (int l = lp; l < LL; l += 4) {
        float wgt = sc[l];
        const uint4* e4 = (const uint4*)(g_enc + ((size_t)l * BB + b) * HH);
        uint4 v = e4[hg];
        const __half2* h2 = (const __half2*)&v;
#pragma unroll
        for (int i = 0; i < 4; i++) {
            float2 f = __half22float2(h2[i]);
            acc[2 * i]     += wgt * f.x;
            acc[2 * i + 1] += wgt * f.y;
        }
    }
#pragma unroll
    for (int i = 0; i < 8; i++) part[lp * 512 + hg * 8 + i] = acc[i];
    __syncthreads();
    float inv = 1.f / red[0];
    if (tid < 64) {
#pragma unroll
        for (int i = 0; i < 8; i++) {
            float v = part[0 * 512 + tid * 8 + i] + part[1 * 512 + tid * 8 + i] +
                      part[2 * 512 + tid * 8 + i] + part[3 * 512 + tid * 8 + i];
            g_ctx[(size_t)b * HH + tid * 8 + i] = rna_tf32(v * inv);
        }
    }
}

__global__ void __launch_bounds__(NTHR, 2) dec_persistent(const float* __restrict__ Wfc,
                                                          const float* __restrict__ bfc,
                                                          float* __restrict__ out) {
    __shared__ float sm[64 * 36 * 2];
    unsigned round = 0;
    int bx = blockIdx.x;
    int tid = threadIdx.x;
    int t = bx * NTHR + tid;

    for (int ds = 0; ds < PL; ds++) {
        attn_phase(ds, bx, Wfc, bfc, out, sm);
        gridbar(&g_bar_dec, round);

        {
            int kh = bx >> 7, j = bx & 127;
            int mt = j >> 5, nt = j & 31;
            if (kh == 0)
                gemm_tile(g_ctx, nullptr, g_Wdir, nullptr, g_gb0, HH, mt * 64, nt * 64, sm);
            else
                gemm_tile(g_h1[ds & 1], nullptr, g_Wdhr, nullptr, g_gb1, HH, mt * 64, nt * 64, sm);
        }
        gridbar(&g_bar_dec, round);

        {
            float* hw = g_h1[(ds + 1) & 1];
#pragma unroll
            for (int it = 0; it < 2; it++) {
                int e = t + it * (NBLK * NTHR);
                int b = e >> 9, n = e & (HH - 1);
                float y = g_yprev[b];
                float gv[4];
#pragma unroll
                for (int gi = 0; gi < 4; gi++) {
                    int j = gi * HH + n;
                    gv[gi] = g_gb0[(size_t)b * G4 + j] + g_gb1[(size_t)b * G4 + j] +
                             g_bcd[j] + g_Wdi0[j] * y;
                }
                float ig = sigf(gv[0]), fg = sigf(gv[1]);
                float gg = tanhf(gv[2]), og = sigf(gv[3]);
                float c = fg * g_c1[e] + ig * gg;
                g_c1[e] = c;
                hw[e] = rna_tf32(og * tanhf(c));
            }
        }
        gridbar(&g_bar_dec, round);
    }

    // final y (step PL-1) from h written by last cell: g_h1[PL & 1] == g_h1[0]
    {
        float* red = sm;
        const float* hd = g_h1[PL & 1] + (size_t)bx * HH;
        red[tid] = hd[tid] * Wfc[tid] + hd[tid + 256] * Wfc[tid + 256];
        __syncthreads();
        for (int off = 128; off; off >>= 1) {
            if (tid < off) red[tid] += red[tid + off];
            __syncthreads();
        }
        if (tid == 0) out[bx * PL + (PL - 1)] = red[0] + bfc[0];
    }
}

extern "C" void kernel_launch(void* const* d_in, const int* in_sizes, int n_in,
                              void* d_out, int out_size) {
    const float* x    = (const float*)d_in[0];
    const float* Wih0 = (const float*)d_in[1];
    const float* Whh0 = (const float*)d_in[2];
    const float* bi0  = (const float*)d_in[3];
    const float* bh0  = (const float*)d_in[4];
    const float* Wih1 = (const float*)d_in[5];
    const float* Whh1 = (const float*)d_in[6];
    const float* bi1  = (const float*)d_in[7];
    const float* bh1  = (const float*)d_in[8];
    const float* Wdi  = (const float*)d_in[9];
    const float* Wdh  = (const float*)d_in[10];
    const float* bdi  = (const float*)d_in[11];
    const float* bdh  = (const float*)d_in[12];
    const float* Wfc  = (const float*)d_in[13];
    const float* bfc  = (const float*)d_in[14];
    float* out = (float*)d_out;

    prep_kernel<<<(G4 * HH + 255) / 256, 256>>>(Whh0, Wih1, Whh1, Wdi, Wdh,
                                                bi0, bh0, bi1, bh1, bdi, bdh);
    enc_persistent<<<NBLK, NTHR>>>(x, Wih0);
    dec_persistent<<<NBLK, NTHR>>>(Wfc, bfc, out);
}